// round 8
// baseline (speedup 1.0000x reference)
#include <cuda_runtime.h>
#include <cuda_bf16.h>
#include <cstdint>

// Problem constants
#define Hh 768
#define Lq 384
#define Bq 2
#define NROWS (Bq * Lq)           // 768 rows of (b, l)
#define M_PAIRS 73920             // 384*385/2
#define NXE (768 * 768)           // X elements
#define NWE (1536 * 768)          // W elements (as 1536 virtual K-major rows)

// Scratch
__device__ float g_A[NROWS * Hh];             // X @ W[:, :768]^T + bias
__device__ float g_Bv[NROWS * Hh];            // X @ W[:, 768:]^T
__device__ __align__(16) __nv_bfloat16 g_Xh[NXE];
__device__ __align__(16) __nv_bfloat16 g_Xl[NXE];
__device__ __align__(16) __nv_bfloat16 g_Wh[NWE];
__device__ __align__(16) __nv_bfloat16 g_Wl[NWE];

__device__ __forceinline__ uint32_t smem_u32(const void* p) {
    uint32_t a;
    asm("{ .reg .u64 t; cvta.to.shared.u64 t, %1; cvt.u32.u64 %0, t; }" : "=r"(a) : "l"(p));
    return a;
}

// fp32 -> (hi, lo) bf16 split
__device__ __forceinline__ void split_bf(float v, __nv_bfloat16& h, __nv_bfloat16& l) {
    h = __float2bfloat16(v);
    l = __float2bfloat16(v - __bfloat162float(h));
}
__device__ __forceinline__ void split4(const float4 v, uint2& hi, uint2& lo) {
    __nv_bfloat16 h0, l0, h1, l1, h2, l2, h3, l3;
    split_bf(v.x, h0, l0); split_bf(v.y, h1, l1);
    split_bf(v.z, h2, l2); split_bf(v.w, h3, l3);
    __nv_bfloat162 ph0(h0, h1), ph1(h2, h3), pl0(l0, l1), pl1(l2, l3);
    hi.x = *reinterpret_cast<uint32_t*>(&ph0);
    hi.y = *reinterpret_cast<uint32_t*>(&ph1);
    lo.x = *reinterpret_cast<uint32_t*>(&pl0);
    lo.y = *reinterpret_cast<uint32_t*>(&pl1);
}

// ---------------------------------------------------------------------------
// Kernel 0: fp32 -> bf16 hi/lo split, 8 elems/thread (2x float4 in flight).
// W re-packed into 1536 K-major virtual rows: row n = p*768+h holds
// W[h, p*768 + k], k in [0,768).
// ---------------------------------------------------------------------------
__global__ __launch_bounds__(256) void convert_kernel(const float* __restrict__ X,
                                                      const float* __restrict__ W) {
    const int e = (blockIdx.x * 256 + threadIdx.x) * 8;
    float4 v0, v1;
    int d0, d1;                 // destination element indices (within Xh or Wh space)
    if (e < NXE) {
        v0 = *reinterpret_cast<const float4*>(X + e);
        v1 = *reinterpret_cast<const float4*>(X + e + 4);
        d0 = e; d1 = e + 4;
        uint2 hi, lo;
        split4(v0, hi, lo);
        *reinterpret_cast<uint2*>(&g_Xh[d0]) = hi;
        *reinterpret_cast<uint2*>(&g_Xl[d0]) = lo;
        split4(v1, hi, lo);
        *reinterpret_cast<uint2*>(&g_Xh[d1]) = hi;
        *reinterpret_cast<uint2*>(&g_Xl[d1]) = lo;
    } else {
        const int e2 = e - NXE;          // 8-aligned, 768 % 8 == 0 -> same row n
        const int n = e2 / 768;
        const int k = e2 - n * 768;
        const int p = (n >= 768);
        const int h = n - p * 768;
        const float* src = W + (size_t)h * 1536 + p * 768 + k;
        v0 = *reinterpret_cast<const float4*>(src);
        v1 = *reinterpret_cast<const float4*>(src + 4);
        uint2 hi, lo;
        split4(v0, hi, lo);
        *reinterpret_cast<uint2*>(&g_Wh[e2]) = hi;
        *reinterpret_cast<uint2*>(&g_Wl[e2]) = lo;
        split4(v1, hi, lo);
        *reinterpret_cast<uint2*>(&g_Wh[e2 + 4]) = hi;
        *reinterpret_cast<uint2*>(&g_Wl[e2 + 4]) = lo;
    }
}

// ---------------------------------------------------------------------------
// Kernel 1: split-bf16 mma.sync GEMM, BK=32, cp.async double-buffered,
// one __syncthreads per K-iteration (24 total). (unchanged from R6 — near
// its HMMA issue floor)
// ---------------------------------------------------------------------------
__device__ __forceinline__ void ldsm4(uint32_t& r0, uint32_t& r1, uint32_t& r2,
                                      uint32_t& r3, uint32_t addr) {
    asm volatile("ldmatrix.sync.aligned.m8n8.x4.shared.b16 {%0,%1,%2,%3}, [%4];"
                 : "=r"(r0), "=r"(r1), "=r"(r2), "=r"(r3) : "r"(addr));
}
__device__ __forceinline__ void mma16816(float* d, const uint32_t* a, const uint32_t* b) {
    asm volatile(
        "mma.sync.aligned.m16n8k16.row.col.f32.bf16.bf16.f32 "
        "{%0,%1,%2,%3}, {%4,%5,%6,%7}, {%8,%9}, {%0,%1,%2,%3};"
        : "+f"(d[0]), "+f"(d[1]), "+f"(d[2]), "+f"(d[3])
        : "r"(a[0]), "r"(a[1]), "r"(a[2]), "r"(a[3]), "r"(b[0]), "r"(b[1]));
}
#define CPA16(dst, src) \
    asm volatile("cp.async.cg.shared.global [%0], [%1], 16;" :: "r"(dst), "l"(src))
#define CPA_COMMIT() asm volatile("cp.async.commit_group;" ::: "memory")
#define CPA_WAIT0()  asm volatile("cp.async.wait_group 0;" ::: "memory")

#define SB_OFF  40960                     // byte offset of B tiles
#define GEMM_SMEM 61440

__global__ __launch_bounds__(256) void mma_gemm(const float* __restrict__ bias) {
    extern __shared__ char smem[];
    const uint32_t S = smem_u32(smem);

    const int tid = threadIdx.x;
    const int wid = tid >> 5, lane = tid & 31;
    const int wm = wid >> 1, wn = wid & 1;        // warp grid 4(m) x 2(n)
    const int col0 = blockIdx.x * 64;             // virtual-W-row tile (0..1535)
    const int row0 = blockIdx.y * 128;            // X-row tile (0..767)
    const int part = (col0 >= Hh);
    const int hb = col0 - part * Hh;

#define SA_ADDR(BUF, HL, ROW, COLSH) \
    (S + (uint32_t)((((BUF) * 2 + (HL)) * 128 + (ROW)) * 80 + (COLSH) * 2))
#define SB_ADDR(BUF, HL, ROW, COLSH) \
    (S + SB_OFF + (uint32_t)((((BUF) * 2 + (HL)) * 64 + (ROW)) * 80 + (COLSH) * 2))

    const int cr = tid >> 2;                      // 0..63
    const int ck = (tid & 3) * 8;                 // k offset in elems
    const size_t aBase0 = (size_t)(row0 + cr) * 768 + ck;
    const size_t aBase1 = (size_t)(row0 + cr + 64) * 768 + ck;
    const size_t bBase  = (size_t)(col0 + cr) * 768 + ck;

    const int aq = lane >> 3, al8 = lane & 7;
    const int a_row = wm * 32 + (aq & 1) * 8 + al8;
    const int a_col = (aq >> 1) * 8;
    const int b_row0 = wn * 32 + (aq >> 1) * 8 + al8;
    const int b_col = (aq & 1) * 8;

    float acc[2][4][4];
#pragma unroll
    for (int i = 0; i < 2; i++)
#pragma unroll
        for (int j = 0; j < 4; j++)
#pragma unroll
            for (int c = 0; c < 4; c++) acc[i][j][c] = 0.0f;

#define PREFETCH(BUF, K0)                                                     \
    do {                                                                      \
        CPA16(SA_ADDR(BUF, 0, cr, ck),      g_Xh + aBase0 + (K0));            \
        CPA16(SA_ADDR(BUF, 0, cr + 64, ck), g_Xh + aBase1 + (K0));            \
        CPA16(SA_ADDR(BUF, 1, cr, ck),      g_Xl + aBase0 + (K0));            \
        CPA16(SA_ADDR(BUF, 1, cr + 64, ck), g_Xl + aBase1 + (K0));            \
        CPA16(SB_ADDR(BUF, 0, cr, ck),      g_Wh + bBase + (K0));             \
        CPA16(SB_ADDR(BUF, 1, cr, ck),      g_Wl + bBase + (K0));             \
        CPA_COMMIT();                                                         \
    } while (0)

    PREFETCH(0, 0);

    for (int t = 0; t < 24; ++t) {
        const int buf = t & 1;
        CPA_WAIT0();
        __syncthreads();
        if (t + 1 < 24) PREFETCH(buf ^ 1, (t + 1) * 32);

#pragma unroll
        for (int ksub = 0; ksub < 2; ++ksub) {
            const int kc = ksub * 16;
            uint32_t Afh[2][4], Afl[2][4];
            uint32_t Bfh[4][2], Bfl[4][2];
#pragma unroll
            for (int fm = 0; fm < 2; fm++) {
                ldsm4(Afh[fm][0], Afh[fm][1], Afh[fm][2], Afh[fm][3],
                      SA_ADDR(buf, 0, a_row + fm * 16, kc + a_col));
                ldsm4(Afl[fm][0], Afl[fm][1], Afl[fm][2], Afl[fm][3],
                      SA_ADDR(buf, 1, a_row + fm * 16, kc + a_col));
            }
#pragma unroll
            for (int fp = 0; fp < 2; fp++) {
                ldsm4(Bfh[fp * 2][0], Bfh[fp * 2][1], Bfh[fp * 2 + 1][0], Bfh[fp * 2 + 1][1],
                      SB_ADDR(buf, 0, b_row0 + fp * 16, kc + b_col));
                ldsm4(Bfl[fp * 2][0], Bfl[fp * 2][1], Bfl[fp * 2 + 1][0], Bfl[fp * 2 + 1][1],
                      SB_ADDR(buf, 1, b_row0 + fp * 16, kc + b_col));
            }
#pragma unroll
            for (int fm = 0; fm < 2; fm++)
#pragma unroll
                for (int fn = 0; fn < 4; fn++) {
                    mma16816(acc[fm][fn], Afh[fm], Bfh[fn]);
                    mma16816(acc[fm][fn], Afh[fm], Bfl[fn]);
                    mma16816(acc[fm][fn], Afl[fm], Bfh[fn]);
                }
        }
    }

    float* dst = part ? g_Bv : g_A;
    const int r_base = row0 + wm * 32 + (lane >> 2);
    const int c_base = hb + wn * 32 + (lane & 3) * 2;
#pragma unroll
    for (int fm = 0; fm < 2; fm++)
#pragma unroll
        for (int fn = 0; fn < 4; fn++) {
            const int cc = c_base + fn * 8;
            float2 b0 = make_float2(0.f, 0.f);
            if (!part) b0 = *reinterpret_cast<const float2*>(bias + cc);
#pragma unroll
            for (int hr = 0; hr < 2; hr++) {
                const int rr = r_base + fm * 16 + hr * 8;
                float2 v;
                v.x = acc[fm][fn][hr * 2 + 0] + b0.x;
                v.y = acc[fm][fn][hr * 2 + 1] + b0.y;
                *reinterpret_cast<float2*>(dst + (size_t)rr * Hh + cc) = v;
            }
        }
}

// ---------------------------------------------------------------------------
// Fast tanh: tanh(z) = 1 - 2/(exp(2z)+1).
// ---------------------------------------------------------------------------
__device__ __forceinline__ float fast_tanh(float z) {
    const float e = __expf(2.0f * z);
    return 1.0f - __fdividef(2.0f, e + 1.0f);
}

// ---------------------------------------------------------------------------
// Kernel 2: out[b, m(i,j), h] = tanh(A[b,i,h] + Bv[b,j,h]) for j >= i.
// IT=4 x JT=8 tile, 192 threads, float4 per thread.
// jj-outer / ii-inner: only a[4] cached in regs; bv loaded per-jj (L2-hot).
// Target ~42 regs -> 8 blocks/SM (~75% occ) to overlap MUFU with DRAM writes.
// ---------------------------------------------------------------------------
__global__ __launch_bounds__(192, 8) void pairs_kernel(float* __restrict__ out) {
    const int b  = blockIdx.z;
    const int i0 = blockIdx.y * 4;
    const int j0 = blockIdx.x * 8;
    if (j0 + 8 <= i0) return;

    const int t = threadIdx.x;
    const int h0 = t * 4;

    float4 a[4];
    float* op[4];
#pragma unroll
    for (int ii = 0; ii < 4; ii++) {
        const int i = i0 + ii;
        a[ii] = *reinterpret_cast<const float4*>(g_A + (size_t)(b * Lq + i) * Hh + h0);
        const int rowbase = i * Lq - (i * (i - 1)) / 2 - i;   // + j gives pair row
        op[ii] = out + (size_t)(b * M_PAIRS + rowbase) * Hh + h0;
    }
    const float* bvp = g_Bv + (size_t)(b * Lq + j0) * Hh + h0;

#pragma unroll
    for (int jj = 0; jj < 8; jj++) {
        const int j = j0 + jj;
        const float4 bv = *reinterpret_cast<const float4*>(bvp + (size_t)jj * Hh);
#pragma unroll
        for (int ii = 0; ii < 4; ii++) {
            if (j >= i0 + ii) {
                float4 v;
                v.x = fast_tanh(a[ii].x + bv.x);
                v.y = fast_tanh(a[ii].y + bv.y);
                v.z = fast_tanh(a[ii].z + bv.z);
                v.w = fast_tanh(a[ii].w + bv.w);
                __stcs(reinterpret_cast<float4*>(op[ii] + (size_t)j * Hh), v);
            }
        }
    }
}

// ---------------------------------------------------------------------------
// Launch: seq_hiddens [2,384,768] f32, W [768,1536] f32, b [768] f32.
// Output [2, 73920, 768] f32.
// ---------------------------------------------------------------------------
extern "C" void kernel_launch(void* const* d_in, const int* in_sizes, int n_in,
                              void* d_out, int out_size) {
    const float* seq  = (const float*)d_in[0];
    const float* W    = (const float*)d_in[1];
    const float* bias = (const float*)d_in[2];
    float* out = (float*)d_out;

    cudaFuncSetAttribute(mma_gemm, cudaFuncAttributeMaxDynamicSharedMemorySize, GEMM_SMEM);

    convert_kernel<<<(NXE + NWE) / 2048, 256>>>(seq, W);

    dim3 g1(24, 6);       // (N/64 over 1536, M/128 over 768) = 144 CTAs
    mma_gemm<<<g1, 256, GEMM_SMEM>>>(bias);

    dim3 g2(48, 96, 2);   // (384/8 j-tiles, 384/4 i-tiles, batch)
    pairs_kernel<<<g2, 192>>>(out);
}

// round 10
// speedup vs baseline: 1.0267x; 1.0267x over previous
#include <cuda_runtime.h>
#include <cuda_bf16.h>
#include <cstdint>

// Problem constants
#define Hh 768
#define Lq 384
#define Bq 2
#define NROWS (Bq * Lq)           // 768 rows of (b, l)
#define M_PAIRS 73920             // 384*385/2
#define NXE (768 * 768)           // X elements
#define NWE (1536 * 768)          // W elements (as 1536 virtual K-major rows)

// Scratch
__device__ float g_A[NROWS * Hh];             // X @ W[:, :768]^T + bias
__device__ float g_Bv[NROWS * Hh];            // X @ W[:, 768:]^T
__device__ __align__(16) __nv_bfloat16 g_Xh[NXE];
__device__ __align__(16) __nv_bfloat16 g_Xl[NXE];
__device__ __align__(16) __nv_bfloat16 g_Wh[NWE];
__device__ __align__(16) __nv_bfloat16 g_Wl[NWE];

__device__ __forceinline__ uint32_t smem_u32(const void* p) {
    uint32_t a;
    asm("{ .reg .u64 t; cvta.to.shared.u64 t, %1; cvt.u32.u64 %0, t; }" : "=r"(a) : "l"(p));
    return a;
}

// fp32 -> (hi, lo) bf16 split
__device__ __forceinline__ void split_bf(float v, __nv_bfloat16& h, __nv_bfloat16& l) {
    h = __float2bfloat16(v);
    l = __float2bfloat16(v - __bfloat162float(h));
}
__device__ __forceinline__ void split4(const float4 v, uint2& hi, uint2& lo) {
    __nv_bfloat16 h0, l0, h1, l1, h2, l2, h3, l3;
    split_bf(v.x, h0, l0); split_bf(v.y, h1, l1);
    split_bf(v.z, h2, l2); split_bf(v.w, h3, l3);
    __nv_bfloat162 ph0(h0, h1), ph1(h2, h3), pl0(l0, l1), pl1(l2, l3);
    hi.x = *reinterpret_cast<uint32_t*>(&ph0);
    hi.y = *reinterpret_cast<uint32_t*>(&ph1);
    lo.x = *reinterpret_cast<uint32_t*>(&pl0);
    lo.y = *reinterpret_cast<uint32_t*>(&pl1);
}

// ---------------------------------------------------------------------------
// Kernel 0: fp32 -> bf16 hi/lo split, 4 elems/thread.
// W re-packed into 1536 K-major virtual rows: row n = p*768+h holds
// W[h, p*768 + k], k in [0,768).
// ---------------------------------------------------------------------------
__global__ __launch_bounds__(256) void convert_kernel(const float* __restrict__ X,
                                                      const float* __restrict__ W) {
    const int e = (blockIdx.x * 256 + threadIdx.x) * 4;
    uint2 hi, lo;
    if (e < NXE) {
        const float4 v = *reinterpret_cast<const float4*>(X + e);
        split4(v, hi, lo);
        *reinterpret_cast<uint2*>(&g_Xh[e]) = hi;
        *reinterpret_cast<uint2*>(&g_Xl[e]) = lo;
    } else {
        const int e2 = e - NXE;
        const int n = e2 / 768;
        const int k = e2 - n * 768;
        const int p = (n >= 768);
        const int h = n - p * 768;
        const float4 v = *reinterpret_cast<const float4*>(W + (size_t)h * 1536 + p * 768 + k);
        split4(v, hi, lo);
        *reinterpret_cast<uint2*>(&g_Wh[e2]) = hi;
        *reinterpret_cast<uint2*>(&g_Wl[e2]) = lo;
    }
}

// ---------------------------------------------------------------------------
// Kernel 1: split-bf16 mma.sync GEMM, BK=32, 4-stage cp.async ring
// (wait_group 2 keeps 3 tiles in flight -> latency amortized over ~3 phases).
// D = Ah*Bh + Ah*Bl + Al*Bh (fp32 accum). CTA tile 128x64, 8 warps (4m x 2n).
// Smem rows: 40 shorts (80 B): 16B-aligned for cp.async, LDSM conflict-free.
// 4 stages x 30720 B = 122880 B dynamic smem. Grid (24, 6) = 144 CTAs.
// ---------------------------------------------------------------------------
__device__ __forceinline__ void ldsm4(uint32_t& r0, uint32_t& r1, uint32_t& r2,
                                      uint32_t& r3, uint32_t addr) {
    asm volatile("ldmatrix.sync.aligned.m8n8.x4.shared.b16 {%0,%1,%2,%3}, [%4];"
                 : "=r"(r0), "=r"(r1), "=r"(r2), "=r"(r3) : "r"(addr));
}
__device__ __forceinline__ void mma16816(float* d, const uint32_t* a, const uint32_t* b) {
    asm volatile(
        "mma.sync.aligned.m16n8k16.row.col.f32.bf16.bf16.f32 "
        "{%0,%1,%2,%3}, {%4,%5,%6,%7}, {%8,%9}, {%0,%1,%2,%3};"
        : "+f"(d[0]), "+f"(d[1]), "+f"(d[2]), "+f"(d[3])
        : "r"(a[0]), "r"(a[1]), "r"(a[2]), "r"(a[3]), "r"(b[0]), "r"(b[1]));
}
#define CPA16(dst, src) \
    asm volatile("cp.async.cg.shared.global [%0], [%1], 16;" :: "r"(dst), "l"(src))
#define CPA_COMMIT() asm volatile("cp.async.commit_group;" ::: "memory")
#define CPA_WAIT2()  asm volatile("cp.async.wait_group 2;" ::: "memory")

#define STAGE_B   30720                   // bytes per pipeline stage
#define SB_OFF    20480                   // B tile offset within a stage
#define GEMM_SMEM (4 * STAGE_B)           // 122880

__global__ __launch_bounds__(256) void mma_gemm(const float* __restrict__ bias) {
    extern __shared__ char smem[];
    const uint32_t S = smem_u32(smem);

    const int tid = threadIdx.x;
    const int wid = tid >> 5, lane = tid & 31;
    const int wm = wid >> 1, wn = wid & 1;        // warp grid 4(m) x 2(n)
    const int col0 = blockIdx.x * 64;             // virtual-W-row tile (0..1535)
    const int row0 = blockIdx.y * 128;            // X-row tile (0..767)
    const int part = (col0 >= Hh);
    const int hb = col0 - part * Hh;

    // Stage-contiguous layout: stage s at S + s*STAGE_B.
    // A: [hl][row(128)][40 shorts]; B at +SB_OFF: [hl][row(64)][40 shorts].
#define SA_ADDR(BUF, HL, ROW, COLSH) \
    (S + (uint32_t)(BUF) * STAGE_B + (uint32_t)((((HL) * 128 + (ROW)) * 80) + (COLSH) * 2))
#define SB_ADDR(BUF, HL, ROW, COLSH) \
    (S + (uint32_t)(BUF) * STAGE_B + SB_OFF + (uint32_t)((((HL) * 64 + (ROW)) * 80) + (COLSH) * 2))

    const int cr = tid >> 2;                      // 0..63
    const int ck = (tid & 3) * 8;                 // k offset in elems
    const size_t aBase0 = (size_t)(row0 + cr) * 768 + ck;
    const size_t aBase1 = (size_t)(row0 + cr + 64) * 768 + ck;
    const size_t bBase  = (size_t)(col0 + cr) * 768 + ck;

    const int aq = lane >> 3, al8 = lane & 7;
    const int a_row = wm * 32 + (aq & 1) * 8 + al8;
    const int a_col = (aq >> 1) * 8;
    const int b_row0 = wn * 32 + (aq >> 1) * 8 + al8;
    const int b_col = (aq & 1) * 8;

    float acc[2][4][4];
#pragma unroll
    for (int i = 0; i < 2; i++)
#pragma unroll
        for (int j = 0; j < 4; j++)
#pragma unroll
            for (int c = 0; c < 4; c++) acc[i][j][c] = 0.0f;

#define PREFETCH(BUF, K0)                                                     \
    do {                                                                      \
        CPA16(SA_ADDR(BUF, 0, cr, ck),      g_Xh + aBase0 + (K0));            \
        CPA16(SA_ADDR(BUF, 0, cr + 64, ck), g_Xh + aBase1 + (K0));            \
        CPA16(SA_ADDR(BUF, 1, cr, ck),      g_Xl + aBase0 + (K0));            \
        CPA16(SA_ADDR(BUF, 1, cr + 64, ck), g_Xl + aBase1 + (K0));            \
        CPA16(SB_ADDR(BUF, 0, cr, ck),      g_Wh + bBase + (K0));             \
        CPA16(SB_ADDR(BUF, 1, cr, ck),      g_Wl + bBase + (K0));             \
        CPA_COMMIT();                                                         \
    } while (0)

    // Prologue: fill 3 of 4 stages.
    PREFETCH(0, 0);
    PREFETCH(1, 32);
    PREFETCH(2, 64);

    for (int t = 0; t < 24; ++t) {
        const int buf = t & 3;
        CPA_WAIT2();                      // stage t landed (own copies)
        __syncthreads();                  // visibility + all warps done with stage (t-1)&3
        if (t + 3 < 24) PREFETCH((t + 3) & 3, (t + 3) * 32);  // overwrites stage (t-1)&3

#pragma unroll
        for (int ksub = 0; ksub < 2; ++ksub) {
            const int kc = ksub * 16;
            uint32_t Afh[2][4], Afl[2][4];
            uint32_t Bfh[4][2], Bfl[4][2];
#pragma unroll
            for (int fm = 0; fm < 2; fm++) {
                ldsm4(Afh[fm][0], Afh[fm][1], Afh[fm][2], Afh[fm][3],
                      SA_ADDR(buf, 0, a_row + fm * 16, kc + a_col));
                ldsm4(Afl[fm][0], Afl[fm][1], Afl[fm][2], Afl[fm][3],
                      SA_ADDR(buf, 1, a_row + fm * 16, kc + a_col));
            }
#pragma unroll
            for (int fp = 0; fp < 2; fp++) {
                ldsm4(Bfh[fp * 2][0], Bfh[fp * 2][1], Bfh[fp * 2 + 1][0], Bfh[fp * 2 + 1][1],
                      SB_ADDR(buf, 0, b_row0 + fp * 16, kc + b_col));
                ldsm4(Bfl[fp * 2][0], Bfl[fp * 2][1], Bfl[fp * 2 + 1][0], Bfl[fp * 2 + 1][1],
                      SB_ADDR(buf, 1, b_row0 + fp * 16, kc + b_col));
            }
#pragma unroll
            for (int fm = 0; fm < 2; fm++)
#pragma unroll
                for (int fn = 0; fn < 4; fn++) {
                    mma16816(acc[fm][fn], Afh[fm], Bfh[fn]);
                    mma16816(acc[fm][fn], Afh[fm], Bfl[fn]);
                    mma16816(acc[fm][fn], Afl[fm], Bfh[fn]);
                }
        }
    }

    // Epilogue: acc -> g_A (with bias) / g_Bv
    float* dst = part ? g_Bv : g_A;
    const int r_base = row0 + wm * 32 + (lane >> 2);
    const int c_base = hb + wn * 32 + (lane & 3) * 2;
#pragma unroll
    for (int fm = 0; fm < 2; fm++)
#pragma unroll
        for (int fn = 0; fn < 4; fn++) {
            const int cc = c_base + fn * 8;
            float2 b0 = make_float2(0.f, 0.f);
            if (!part) b0 = *reinterpret_cast<const float2*>(bias + cc);
#pragma unroll
            for (int hr = 0; hr < 2; hr++) {
                const int rr = r_base + fm * 16 + hr * 8;
                float2 v;
                v.x = acc[fm][fn][hr * 2 + 0] + b0.x;
                v.y = acc[fm][fn][hr * 2 + 1] + b0.y;
                *reinterpret_cast<float2*>(dst + (size_t)rr * Hh + cc) = v;
            }
        }
}

// ---------------------------------------------------------------------------
// Fast tanh: tanh(z) = 1 - 2/(exp(2z)+1).
// ---------------------------------------------------------------------------
__device__ __forceinline__ float fast_tanh(float z) {
    const float e = __expf(2.0f * z);
    return 1.0f - __fdividef(2.0f, e + 1.0f);
}

// ---------------------------------------------------------------------------
// Kernel 2 (R6 version — at the HBM write floor, do not touch):
// out[b, m(i,j), h] = tanh(A[b,i,h] + Bv[b,j,h]) for j >= i.
// IT=4 x JT=8 tile, 192 threads, float4 per thread, ii-outer with bv cached.
// ---------------------------------------------------------------------------
__global__ __launch_bounds__(192) void pairs_kernel(float* __restrict__ out) {
    const int b  = blockIdx.z;
    const int i0 = blockIdx.y * 4;
    const int j0 = blockIdx.x * 8;
    if (j0 + 8 <= i0) return;

    const int t = threadIdx.x;
    const int h0 = t * 4;

    float4 a[4];
#pragma unroll
    for (int ii = 0; ii < 4; ii++)
        a[ii] = *reinterpret_cast<const float4*>(g_A + (size_t)(b * Lq + i0 + ii) * Hh + h0);

    float4 bv[8];
#pragma unroll
    for (int jj = 0; jj < 8; jj++)
        bv[jj] = *reinterpret_cast<const float4*>(g_Bv + (size_t)(b * Lq + j0 + jj) * Hh + h0);

#pragma unroll
    for (int ii = 0; ii < 4; ii++) {
        const int i = i0 + ii;
        const int rowbase = i * Lq - (i * (i - 1)) / 2 - i;
        float* obase = out + ((size_t)(b * M_PAIRS + rowbase + j0)) * Hh + h0;
#pragma unroll
        for (int jj = 0; jj < 8; jj++) {
            const int j = j0 + jj;
            if (j >= i) {
                float4 v;
                v.x = fast_tanh(a[ii].x + bv[jj].x);
                v.y = fast_tanh(a[ii].y + bv[jj].y);
                v.z = fast_tanh(a[ii].z + bv[jj].z);
                v.w = fast_tanh(a[ii].w + bv[jj].w);
                __stcs(reinterpret_cast<float4*>(obase + (size_t)jj * Hh), v);
            }
        }
    }
}

// ---------------------------------------------------------------------------
// Launch: seq_hiddens [2,384,768] f32, W [768,1536] f32, b [768] f32.
// Output [2, 73920, 768] f32.
// ---------------------------------------------------------------------------
extern "C" void kernel_launch(void* const* d_in, const int* in_sizes, int n_in,
                              void* d_out, int out_size) {
    const float* seq  = (const float*)d_in[0];
    const float* W    = (const float*)d_in[1];
    const float* bias = (const float*)d_in[2];
    float* out = (float*)d_out;

    cudaFuncSetAttribute(mma_gemm, cudaFuncAttributeMaxDynamicSharedMemorySize, GEMM_SMEM);

    convert_kernel<<<(NXE + NWE) / 1024, 256>>>(seq, W);

    dim3 g1(24, 6);       // (N/64 over 1536, M/128 over 768) = 144 CTAs
    mma_gemm<<<g1, 256, GEMM_SMEM>>>(bias);

    dim3 g2(48, 96, 2);   // (384/8 j-tiles, 384/4 i-tiles, batch)
    pairs_kernel<<<g2, 192>>>(out);
}

// round 11
// speedup vs baseline: 1.1718x; 1.1413x over previous
#include <cuda_runtime.h>
#include <cuda_fp16.h>
#include <cstdint>

// Problem constants
#define Hh 768
#define Lq 384
#define Bq 2
#define NROWS (Bq * Lq)           // 768 rows of (b, l)
#define M_PAIRS 73920             // 384*385/2
#define NXE (768 * 768)           // X elements
#define NWE (1536 * 768)          // W elements (as 1536 virtual K-major rows)

// Scratch
__device__ float g_A[NROWS * Hh];             // X @ W[:, :768]^T + bias
__device__ float g_Bv[NROWS * Hh];            // X @ W[:, 768:]^T
__device__ __align__(16) __half g_Xh[NXE];
__device__ __align__(16) __half g_Wh[NWE];

__device__ __forceinline__ uint32_t smem_u32(const void* p) {
    uint32_t a;
    asm("{ .reg .u64 t; cvta.to.shared.u64 t, %1; cvt.u32.u64 %0, t; }" : "=r"(a) : "l"(p));
    return a;
}

// Pack 4 floats -> 4 fp16 (rn) in a uint2
__device__ __forceinline__ uint2 cvt4h(const float4 v) {
    __half2 p0 = __floats2half2_rn(v.x, v.y);
    __half2 p1 = __floats2half2_rn(v.z, v.w);
    uint2 r;
    r.x = *reinterpret_cast<uint32_t*>(&p0);
    r.y = *reinterpret_cast<uint32_t*>(&p1);
    return r;
}

// ---------------------------------------------------------------------------
// Kernel 0: fp32 -> fp16 convert, 4 elems/thread.
// W re-packed into 1536 K-major virtual rows: row n = p*768+h holds
// W[h, p*768 + k], k in [0,768).
// ---------------------------------------------------------------------------
__global__ __launch_bounds__(256) void convert_kernel(const float* __restrict__ X,
                                                      const float* __restrict__ W) {
    const int e = (blockIdx.x * 256 + threadIdx.x) * 4;
    if (e < NXE) {
        const float4 v = *reinterpret_cast<const float4*>(X + e);
        *reinterpret_cast<uint2*>(&g_Xh[e]) = cvt4h(v);
    } else {
        const int e2 = e - NXE;
        const int n = e2 / 768;
        const int k = e2 - n * 768;
        const int p = (n >= 768);
        const int h = n - p * 768;
        const float4 v = *reinterpret_cast<const float4*>(W + (size_t)h * 1536 + p * 768 + k);
        *reinterpret_cast<uint2*>(&g_Wh[e2]) = cvt4h(v);
    }
}

// ---------------------------------------------------------------------------
// Kernel 1: single-pass fp16 mma.sync GEMM (fp32 accumulate), BK=32,
// 4-stage cp.async ring (wait_group 2 -> 3 tiles in flight).
// D[m,n] = sum_k Xh[m,k] * Wh[n,k].  CTA tile 128x64, 8 warps (4m x 2n).
// Smem rows: 40 shorts (80 B): 16B-aligned for cp.async, LDSM conflict-free.
// 4 stages x 15360 B = 61440 B dynamic smem. Grid (24, 6) = 144 CTAs.
// ---------------------------------------------------------------------------
__device__ __forceinline__ void ldsm4(uint32_t& r0, uint32_t& r1, uint32_t& r2,
                                      uint32_t& r3, uint32_t addr) {
    asm volatile("ldmatrix.sync.aligned.m8n8.x4.shared.b16 {%0,%1,%2,%3}, [%4];"
                 : "=r"(r0), "=r"(r1), "=r"(r2), "=r"(r3) : "r"(addr));
}
__device__ __forceinline__ void mma16816(float* d, const uint32_t* a, const uint32_t* b) {
    asm volatile(
        "mma.sync.aligned.m16n8k16.row.col.f32.f16.f16.f32 "
        "{%0,%1,%2,%3}, {%4,%5,%6,%7}, {%8,%9}, {%0,%1,%2,%3};"
        : "+f"(d[0]), "+f"(d[1]), "+f"(d[2]), "+f"(d[3])
        : "r"(a[0]), "r"(a[1]), "r"(a[2]), "r"(a[3]), "r"(b[0]), "r"(b[1]));
}
#define CPA16(dst, src) \
    asm volatile("cp.async.cg.shared.global [%0], [%1], 16;" :: "r"(dst), "l"(src))
#define CPA_COMMIT() asm volatile("cp.async.commit_group;" ::: "memory")
#define CPA_WAIT2()  asm volatile("cp.async.wait_group 2;" ::: "memory")

#define STAGE_B   15360                   // bytes per pipeline stage
#define SB_OFF    10240                   // B tile offset within a stage
#define GEMM_SMEM (4 * STAGE_B)           // 61440

__global__ __launch_bounds__(256) void mma_gemm(const float* __restrict__ bias) {
    extern __shared__ char smem[];
    const uint32_t S = smem_u32(smem);

    const int tid = threadIdx.x;
    const int wid = tid >> 5, lane = tid & 31;
    const int wm = wid >> 1, wn = wid & 1;        // warp grid 4(m) x 2(n)
    const int col0 = blockIdx.x * 64;             // virtual-W-row tile (0..1535)
    const int row0 = blockIdx.y * 128;            // X-row tile (0..767)
    const int part = (col0 >= Hh);
    const int hb = col0 - part * Hh;

    // Stage s at S + s*STAGE_B. A: [row(128)][40 shorts]; B at +SB_OFF: [row(64)][40].
#define SA_ADDR(BUF, ROW, COLSH) \
    (S + (uint32_t)(BUF) * STAGE_B + (uint32_t)((ROW) * 80 + (COLSH) * 2))
#define SB_ADDR(BUF, ROW, COLSH) \
    (S + (uint32_t)(BUF) * STAGE_B + SB_OFF + (uint32_t)((ROW) * 80 + (COLSH) * 2))

    const int cr = tid >> 2;                      // 0..63
    const int ck = (tid & 3) * 8;                 // k offset in elems
    const size_t aBase0 = (size_t)(row0 + cr) * 768 + ck;
    const size_t aBase1 = (size_t)(row0 + cr + 64) * 768 + ck;
    const size_t bBase  = (size_t)(col0 + cr) * 768 + ck;

    const int aq = lane >> 3, al8 = lane & 7;
    const int a_row = wm * 32 + (aq & 1) * 8 + al8;
    const int a_col = (aq >> 1) * 8;
    const int b_row0 = wn * 32 + (aq >> 1) * 8 + al8;
    const int b_col = (aq & 1) * 8;

    float acc[2][4][4];
#pragma unroll
    for (int i = 0; i < 2; i++)
#pragma unroll
        for (int j = 0; j < 4; j++)
#pragma unroll
            for (int c = 0; c < 4; c++) acc[i][j][c] = 0.0f;

#define PREFETCH(BUF, K0)                                                     \
    do {                                                                      \
        CPA16(SA_ADDR(BUF, cr, ck),      g_Xh + aBase0 + (K0));               \
        CPA16(SA_ADDR(BUF, cr + 64, ck), g_Xh + aBase1 + (K0));               \
        CPA16(SB_ADDR(BUF, cr, ck),      g_Wh + bBase + (K0));                \
        CPA_COMMIT();                                                         \
    } while (0)

    // Prologue: fill 3 of 4 stages.
    PREFETCH(0, 0);
    PREFETCH(1, 32);
    PREFETCH(2, 64);

    for (int t = 0; t < 24; ++t) {
        const int buf = t & 3;
        CPA_WAIT2();                      // stage t landed
        __syncthreads();                  // all warps done with stage (t-1)&3
        if (t + 3 < 24) PREFETCH((t + 3) & 3, (t + 3) * 32);

#pragma unroll
        for (int ksub = 0; ksub < 2; ++ksub) {
            const int kc = ksub * 16;
            uint32_t Af[2][4];
            uint32_t Bf[4][2];
#pragma unroll
            for (int fm = 0; fm < 2; fm++)
                ldsm4(Af[fm][0], Af[fm][1], Af[fm][2], Af[fm][3],
                      SA_ADDR(buf, a_row + fm * 16, kc + a_col));
#pragma unroll
            for (int fp = 0; fp < 2; fp++)
                ldsm4(Bf[fp * 2][0], Bf[fp * 2][1], Bf[fp * 2 + 1][0], Bf[fp * 2 + 1][1],
                      SB_ADDR(buf, b_row0 + fp * 16, kc + b_col));
#pragma unroll
            for (int fm = 0; fm < 2; fm++)
#pragma unroll
                for (int fn = 0; fn < 4; fn++)
                    mma16816(acc[fm][fn], Af[fm], Bf[fn]);
        }
    }

    // Epilogue: acc -> g_A (with bias) / g_Bv
    float* dst = part ? g_Bv : g_A;
    const int r_base = row0 + wm * 32 + (lane >> 2);
    const int c_base = hb + wn * 32 + (lane & 3) * 2;
#pragma unroll
    for (int fm = 0; fm < 2; fm++)
#pragma unroll
        for (int fn = 0; fn < 4; fn++) {
            const int cc = c_base + fn * 8;
            float2 b0 = make_float2(0.f, 0.f);
            if (!part) b0 = *reinterpret_cast<const float2*>(bias + cc);
#pragma unroll
            for (int hr = 0; hr < 2; hr++) {
                const int rr = r_base + fm * 16 + hr * 8;
                float2 v;
                v.x = acc[fm][fn][hr * 2 + 0] + b0.x;
                v.y = acc[fm][fn][hr * 2 + 1] + b0.y;
                *reinterpret_cast<float2*>(dst + (size_t)rr * Hh + cc) = v;
            }
        }
}

// ---------------------------------------------------------------------------
// Fast tanh: tanh(z) = 1 - 2/(exp(2z)+1).
// ---------------------------------------------------------------------------
__device__ __forceinline__ float fast_tanh(float z) {
    const float e = __expf(2.0f * z);
    return 1.0f - __fdividef(2.0f, e + 1.0f);
}

// ---------------------------------------------------------------------------
// Kernel 2 (at the HBM write floor — do not touch):
// out[b, m(i,j), h] = tanh(A[b,i,h] + Bv[b,j,h]) for j >= i.
// IT=4 x JT=8 tile, 192 threads, float4 per thread, ii-outer with bv cached.
// ---------------------------------------------------------------------------
__global__ __launch_bounds__(192) void pairs_kernel(float* __restrict__ out) {
    const int b  = blockIdx.z;
    const int i0 = blockIdx.y * 4;
    const int j0 = blockIdx.x * 8;
    if (j0 + 8 <= i0) return;

    const int t = threadIdx.x;
    const int h0 = t * 4;

    float4 a[4];
#pragma unroll
    for (int ii = 0; ii < 4; ii++)
        a[ii] = *reinterpret_cast<const float4*>(g_A + (size_t)(b * Lq + i0 + ii) * Hh + h0);

    float4 bv[8];
#pragma unroll
    for (int jj = 0; jj < 8; jj++)
        bv[jj] = *reinterpret_cast<const float4*>(g_Bv + (size_t)(b * Lq + j0 + jj) * Hh + h0);

#pragma unroll
    for (int ii = 0; ii < 4; ii++) {
        const int i = i0 + ii;
        const int rowbase = i * Lq - (i * (i - 1)) / 2 - i;
        float* obase = out + ((size_t)(b * M_PAIRS + rowbase + j0)) * Hh + h0;
#pragma unroll
        for (int jj = 0; jj < 8; jj++) {
            const int j = j0 + jj;
            if (j >= i) {
                float4 v;
                v.x = fast_tanh(a[ii].x + bv[jj].x);
                v.y = fast_tanh(a[ii].y + bv[jj].y);
                v.z = fast_tanh(a[ii].z + bv[jj].z);
                v.w = fast_tanh(a[ii].w + bv[jj].w);
                __stcs(reinterpret_cast<float4*>(obase + (size_t)jj * Hh), v);
            }
        }
    }
}

// ---------------------------------------------------------------------------
// Launch: seq_hiddens [2,384,768] f32, W [768,1536] f32, b [768] f32.
// Output [2, 73920, 768] f32.
// ---------------------------------------------------------------------------
extern "C" void kernel_launch(void* const* d_in, const int* in_sizes, int n_in,
                              void* d_out, int out_size) {
    const float* seq  = (const float*)d_in[0];
    const float* W    = (const float*)d_in[1];
    const float* bias = (const float*)d_in[2];
    float* out = (float*)d_out;

    cudaFuncSetAttribute(mma_gemm, cudaFuncAttributeMaxDynamicSharedMemorySize, GEMM_SMEM);

    convert_kernel<<<(NXE + NWE) / 1024, 256>>>(seq, W);

    dim3 g1(24, 6);       // (N/64 over 1536, M/128 over 768) = 144 CTAs
    mma_gemm<<<g1, 256, GEMM_SMEM>>>(bias);

    dim3 g2(48, 96, 2);   // (384/8 j-tiles, 384/4 i-tiles, batch)
    pairs_kernel<<<g2, 192>>>(out);
}